// round 2
// baseline (speedup 1.0000x reference)
#include <cuda_runtime.h>
#include <math.h>

#define NN 8192
#define DD 256
#define UU 128
#define BM 64
#define BN 64

typedef unsigned long long u64;

// ---------------- device scratch (no allocations allowed) ----------------
__device__ float g_x [NN * UU];   // x = expmap0(features @ kernel), row-major
__device__ float g_xT[UU * NN];   // transpose of g_x
__device__ float g_x2[NN];        // ||x_i||^2
__device__ float g_buf[NN * UU];  // stage1 temp (u), then flash output (mx)

// ---------------- packed f32x2 helpers ----------------
__device__ __forceinline__ u64 ffma2(u64 a, u64 b, u64 c) {
    u64 d;
    asm("fma.rn.f32x2 %0, %1, %2, %3;" : "=l"(d) : "l"(a), "l"(b), "l"(c));
    return d;
}
__device__ __forceinline__ u64 pack2(float lo, float hi) {
    u64 d;
    asm("mov.b64 %0, {%1, %2};" : "=l"(d) : "f"(lo), "f"(hi));
    return d;
}
__device__ __forceinline__ float2 unpack2(u64 v) {
    float lo, hi;
    asm("mov.b64 {%0, %1}, %2;" : "=f"(lo), "=f"(hi) : "l"(v));
    return make_float2(lo, hi);
}

// ============================================================
// Stage 1: u = features @ kernel   [8192,256]@[256,128]
// ============================================================
__global__ __launch_bounds__(256) void k_gemmA(const float* __restrict__ feat,
                                               const float* __restrict__ W) {
    __shared__ float fs[16][DD];
    int tid = threadIdx.x;
    int r0  = blockIdx.x * 16;
    for (int idx = tid; idx < 16 * DD; idx += 256)
        fs[idx >> 8][idx & 255] = feat[(size_t)(r0 + (idx >> 8)) * DD + (idx & 255)];
    __syncthreads();

    int col = tid & 127;
    int rg  = tid >> 7;
    float acc[8] = {0.f,0.f,0.f,0.f,0.f,0.f,0.f,0.f};
    for (int d = 0; d < DD; d++) {
        float kv = W[d * UU + col];
        #pragma unroll
        for (int r = 0; r < 8; r++)
            acc[r] = fmaf(fs[rg * 8 + r][d], kv, acc[r]);
    }
    #pragma unroll
    for (int r = 0; r < 8; r++)
        g_buf[(size_t)(r0 + rg * 8 + r) * UU + col] = acc[r];
}

// ============================================================
__device__ __forceinline__ float blockReduce128(float v, volatile float* sm) {
    #pragma unroll
    for (int o = 16; o > 0; o >>= 1) v += __shfl_xor_sync(0xffffffffu, v, o);
    if ((threadIdx.x & 31) == 0) sm[threadIdx.x >> 5] = v;
    __syncthreads();
    float r = sm[0] + sm[1] + sm[2] + sm[3];
    __syncthreads();
    return r;
}

// ============================================================
// Stage 2: x = expmap0(u); also write xT and x2
// ============================================================
__global__ __launch_bounds__(128) void k_expmap() {
    __shared__ float sm[4];
    int row = blockIdx.x, t = threadIdx.x;
    float v  = g_buf[(size_t)row * UU + t];
    float n2 = blockReduce128(v * v, sm);
    float n  = fmaxf(sqrtf(n2), 1e-15f);
    float fac = tanhf(n) / n;
    float xv = fac * v;
    g_x [(size_t)row * UU + t] = xv;
    g_xT[(size_t)t * NN + row] = xv;
    float s2 = blockReduce128(xv * xv, sm);
    if (t == 0) g_x2[row] = s2;
}

// ============================================================
// Stage 3: fused flash attention, FFMA2 (fma.rn.f32x2) version.
//   Xip/Xjp: k-pair interleaved layouts [kp][node*2 + (k&1)]
//   GEMM1 accumulates f32x2 over k-pairs
//   GEMM2 accumulates f32x2 over d-pairs (w replicated to both halves)
// ============================================================
#define SM_XIP 0
#define SM_XJP (SM_XIP + UU * BM)
#define SM_XJS (SM_XJP + UU * BN)
#define SM_WS  (SM_XJS + BN * UU)
#define SM_X2I (SM_WS + BM * 68)
#define SM_X2J (SM_X2I + BM)
#define SMEM_FLOATS (SM_X2J + BN)
#define SMEM_BYTES (SMEM_FLOATS * 4)

__global__ __launch_bounds__(256) void k_flash(const int* __restrict__ adj) {
    extern __shared__ float smem[];
    float* Xip   = smem + SM_XIP;   // [64 kp][128] : (kp,i) pair-interleaved
    float* Xjp   = smem + SM_XJP;   // [64 kp][128] : (kp,j) pair-interleaved
    float* Xjs   = smem + SM_XJS;   // [64 j][128 d]
    float* Ws    = smem + SM_WS;    // [64][68]
    float* x2i_s = smem + SM_X2I;
    float* x2j_s = smem + SM_X2J;

    int tid = threadIdx.x;
    int tx = tid & 15, ty = tid >> 4;
    int i0 = blockIdx.x * BM;

    // load Xi tile into k-pair-interleaved layout (once per block)
    for (int idx = tid; idx < UU * BM; idx += 256) {
        int k = idx >> 6, i = idx & 63;
        Xip[(k >> 1) * 128 + i * 2 + (k & 1)] = g_xT[(size_t)k * NN + i0 + i];
    }
    if (tid < BM) x2i_s[tid] = g_x2[i0 + tid];
    __syncthreads();

    float x2i[4];
    #pragma unroll
    for (int r = 0; r < 4; r++) x2i[r] = x2i_s[ty * 4 + r];

    u64 o2[4][4];              // output accumulators, d-pairs
    const u64 Z = 0ull;
    #pragma unroll
    for (int r = 0; r < 4; r++)
        #pragma unroll
        for (int d = 0; d < 4; d++) o2[r][d] = Z;
    float rsum[4] = {0.f, 0.f, 0.f, 0.f};

    for (int j0 = 0; j0 < NN; j0 += BN) {
        __syncthreads();   // previous GEMM2 done reading Xjs/Ws
        // ---- load Xj tiles + x2j ----
        for (int idx = tid; idx < UU * BN; idx += 256) {
            int k = idx >> 6, j = idx & 63;
            Xjp[(k >> 1) * 128 + j * 2 + (k & 1)] = g_xT[(size_t)k * NN + j0 + j];
        }
        for (int idx = tid; idx < BN * (UU / 4); idx += 256) {
            int j = idx >> 5, kq = idx & 31;
            float4 v = ((const float4*)g_x)[(size_t)(j0 + j) * (UU / 4) + kq];
            *(float4*)(Xjs + j * UU + kq * 4) = v;
        }
        if (tid < BN) x2j_s[tid] = g_x2[j0 + tid];
        int4 av[4];
        #pragma unroll
        for (int r = 0; r < 4; r++)
            av[r] = *(const int4*)&adj[(size_t)(i0 + ty * 4 + r) * NN + j0 + tx * 4];
        __syncthreads();

        // ---- GEMM1: packed over k-pairs ----
        u64 s2[4][4];
        #pragma unroll
        for (int r = 0; r < 4; r++)
            #pragma unroll
            for (int c = 0; c < 4; c++) s2[r][c] = Z;

        #pragma unroll 4
        for (int kp = 0; kp < UU / 2; kp++) {
            ulonglong2 aA = *(const ulonglong2*)(Xip + kp * 128 + ty * 8);
            ulonglong2 aB = *(const ulonglong2*)(Xip + kp * 128 + ty * 8 + 4);
            ulonglong2 bA = *(const ulonglong2*)(Xjp + kp * 128 + tx * 8);
            ulonglong2 bB = *(const ulonglong2*)(Xjp + kp * 128 + tx * 8 + 4);
            u64 af[4] = {aA.x, aA.y, aB.x, aB.y};
            u64 bf[4] = {bA.x, bA.y, bB.x, bB.y};
            #pragma unroll
            for (int r = 0; r < 4; r++)
                #pragma unroll
                for (int c = 0; c < 4; c++)
                    s2[r][c] = ffma2(af[r], bf[c], s2[r][c]);
        }

        // ---- score function ----
        float x2jv[4];
        #pragma unroll
        for (int c = 0; c < 4; c++) x2jv[c] = x2j_s[tx * 4 + c];

        #pragma unroll
        for (int r = 0; r < 4; r++) {
            int am[4] = {av[r].x, av[r].y, av[r].z, av[r].w};
            float wv[4];
            #pragma unroll
            for (int c = 0; c < 4; c++) {
                float2 sp = unpack2(s2[r][c]);
                float xy = sp.x + sp.y;
                float A  = 1.f - 2.f * xy + x2jv[c];
                float B  = 1.f - x2i[r];
                float num = fmaf(A * A, x2i[r],
                             fmaf(-2.f * A * B, xy, B * B * x2jv[c]));
                num = fmaxf(num, 0.f);
                float den = fmaxf(fmaf(x2i[r], x2jv[c], 1.f - 2.f * xy), 1e-15f);
                float sq  = sqrtf(num);
                float w;
                if (sq < (1.f - 1e-7f) * den)
                    w = (den + sq) / (den - sq);
                else
                    w = (2.f - 1e-7f) / 1e-7f;
                if (am[c] == 0 || !(sq > 0.f)) w = 0.f;
                wv[c] = w;
                rsum[r] += w;
            }
            *(float4*)(Ws + (ty * 4 + r) * 68 + tx * 4) =
                make_float4(wv[0], wv[1], wv[2], wv[3]);
        }
        __syncthreads();

        // ---- GEMM2: packed over d-pairs ----
        #pragma unroll 2
        for (int j = 0; j < BN; j++) {
            ulonglong2 bA = *(const ulonglong2*)(Xjs + j * UU + tx * 8);
            ulonglong2 bB = *(const ulonglong2*)(Xjs + j * UU + tx * 8 + 4);
            u64 bf[4] = {bA.x, bA.y, bB.x, bB.y};
            #pragma unroll
            for (int r = 0; r < 4; r++) {
                float w = Ws[(ty * 4 + r) * 68 + j];
                u64 w2 = pack2(w, w);
                #pragma unroll
                for (int d = 0; d < 4; d++)
                    o2[r][d] = ffma2(w2, bf[d], o2[r][d]);
            }
        }
    }

    // ---- row-sum reduction, normalize, write mx ----
    __syncthreads();
    #pragma unroll
    for (int r = 0; r < 4; r++) Ws[(ty * 4 + r) * 68 + tx] = rsum[r];
    __syncthreads();
    #pragma unroll
    for (int r = 0; r < 4; r++) {
        float t = 0.f;
        #pragma unroll
        for (int q = 0; q < 16; q++) t += Ws[(ty * 4 + r) * 68 + q];
        float inv = 1.f / t;
        #pragma unroll
        for (int d = 0; d < 4; d++) {
            float2 ov = unpack2(o2[r][d]);
            g_buf[(size_t)(i0 + ty * 4 + r) * UU + tx * 8 + 2 * d]     = ov.x * inv;
            g_buf[(size_t)(i0 + ty * 4 + r) * UU + tx * 8 + 2 * d + 1] = ov.y * inv;
        }
    }
}

// ============================================================
// Stage 4: hyperbolic rescale + mobius bias add
// ============================================================
__global__ __launch_bounds__(128) void k_epilogue(const float* __restrict__ bias,
                                                  float* __restrict__ out) {
    __shared__ float sm[4];
    int row = blockIdx.x, t = threadIdx.x;

    float m   = g_buf[(size_t)row * UU + t];
    float mn2 = blockReduce128(m * m, sm);
    float x2i = g_x2[row];
    float x_n  = fmaxf(sqrtf(x2i), 1e-15f);
    float mx_n = fmaxf(sqrtf(mn2), 1e-15f);
    float xa   = fminf(x_n, 1.f - 1e-7f);
    float art  = 0.5f * (log1pf(xa) - log1pf(-xa));
    float alpha = tanhf(mx_n / x_n * art) / mx_n;
    float ov = alpha * m;

    float bv  = bias[t];
    float bn2 = blockReduce128(bv * bv, sm);
    float bn  = fmaxf(sqrtf(bn2), 1e-15f);
    float bvx = tanhf(bn) / bn * bv;

    float y2  = blockReduce128(bvx * bvx, sm);
    float xy  = blockReduce128(ov * bvx, sm);
    float x2o = blockReduce128(ov * ov, sm);
    float cx  = 1.f + 2.f * xy + y2;
    float cy  = 1.f - x2o;
    float den = fmaxf(fmaf(x2o, y2, 1.f + 2.f * xy), 1e-15f);
    out[(size_t)row * UU + t] = (cx * ov + cy * bvx) / den;
}

// ============================================================
extern "C" void kernel_launch(void* const* d_in, const int* in_sizes, int n_in,
                              void* d_out, int out_size) {
    const float* feat = (const float*)d_in[0];
    const int*   adj  = (const int*)  d_in[1];
    const float* W    = (const float*)d_in[2];
    const float* bias = (const float*)d_in[3];
    float* out = (float*)d_out;

    cudaFuncSetAttribute(k_flash, cudaFuncAttributeMaxDynamicSharedMemorySize,
                         SMEM_BYTES);

    k_gemmA   <<<NN / 16, 256>>>(feat, W);
    k_expmap  <<<NN, 128>>>();
    k_flash   <<<NN / BM, 256, SMEM_BYTES>>>(adj);
    k_epilogue<<<NN, 128>>>(bias, out);
}

// round 4
// speedup vs baseline: 1.9144x; 1.9144x over previous
#include <cuda_runtime.h>
#include <cuda_bf16.h>
#include <cuda_fp16.h>
#include <cstdint>
#include <math.h>

#define NN 8192
#define DD 256
#define UU 128

// ================= device scratch (no allocations allowed) =================
__device__ __align__(256) float          g_buf[NN * UU];     // stage1: u = feat@W
__device__ __align__(256) __half         g_xh[NN * UU];      // fp16 split of x (node-major)
__device__ __align__(256) __half         g_xl[NN * UU];
__device__ __align__(256) __nv_bfloat16  g_xTh[UU * NN];     // bf16 split of x, transposed
__device__ __align__(256) __nv_bfloat16  g_xTl[UU * NN];
__device__ __align__(256) float          g_x2[NN];
__device__ __align__(256) unsigned int   g_w[(size_t)NN * NN];   // packed (w_hi | w_lo<<16) bf16
__device__ __align__(256) float          g_rsump[NN * 64];       // per (i, j-tile) partial sums
__device__ __align__(256) float          g_mx2[2 * NN * UU];     // ksplit halves of mx

// ======================= helpers =======================
__device__ __forceinline__ uint32_t smem_to_u32(const void* p) {
    uint32_t a;
    asm("{ .reg .u64 t; cvta.to.shared.u64 t, %1; cvt.u32.u64 %0, t; }"
        : "=r"(a) : "l"(p));
    return a;
}
__device__ __forceinline__ void ldsm4(uint32_t& r0, uint32_t& r1, uint32_t& r2,
                                      uint32_t& r3, uint32_t addr) {
    asm volatile("ldmatrix.sync.aligned.m8n8.x4.shared.b16 {%0,%1,%2,%3}, [%4];"
                 : "=r"(r0), "=r"(r1), "=r"(r2), "=r"(r3) : "r"(addr));
}
__device__ __forceinline__ void mma_f16(float* d, const uint32_t* a,
                                        uint32_t b0, uint32_t b1) {
    asm volatile("mma.sync.aligned.m16n8k16.row.col.f32.f16.f16.f32 "
                 "{%0,%1,%2,%3}, {%4,%5,%6,%7}, {%8,%9}, {%0,%1,%2,%3};"
                 : "+f"(d[0]), "+f"(d[1]), "+f"(d[2]), "+f"(d[3])
                 : "r"(a[0]), "r"(a[1]), "r"(a[2]), "r"(a[3]), "r"(b0), "r"(b1));
}
__device__ __forceinline__ void mma_bf16(float* d, const uint32_t* a,
                                         uint32_t b0, uint32_t b1) {
    asm volatile("mma.sync.aligned.m16n8k16.row.col.f32.bf16.bf16.f32 "
                 "{%0,%1,%2,%3}, {%4,%5,%6,%7}, {%8,%9}, {%0,%1,%2,%3};"
                 : "+f"(d[0]), "+f"(d[1]), "+f"(d[2]), "+f"(d[3])
                 : "r"(a[0]), "r"(a[1]), "r"(a[2]), "r"(a[3]), "r"(b0), "r"(b1));
}

__device__ __forceinline__ float blockReduce128(float v, volatile float* sm) {
    #pragma unroll
    for (int o = 16; o > 0; o >>= 1) v += __shfl_xor_sync(0xffffffffu, v, o);
    if ((threadIdx.x & 31) == 0) sm[threadIdx.x >> 5] = v;
    __syncthreads();
    float r = sm[0] + sm[1] + sm[2] + sm[3];
    __syncthreads();
    return r;
}

// w = exp(hyperbolic distance), closed form; masked by adjacency / dist==0
__device__ __forceinline__ float score_w(float xy, float x2i, float x2j, int am) {
    float A = 1.f - 2.f * xy + x2j;
    float B = 1.f - x2i;
    float num = fmaf(A * A, x2i, fmaf(-2.f * A * B, xy, B * B * x2j));
    num = fmaxf(num, 0.f);
    float den = fmaxf(fmaf(x2i, x2j, 1.f - 2.f * xy), 1e-15f);
    float sq  = sqrtf(num);
    float w;
    if (sq < (1.f - 1e-7f) * den) w = (den + sq) / (den - sq);
    else                          w = (2.f - 1e-7f) / 1e-7f;
    if (am == 0 || !(sq > 0.f)) w = 0.f;
    return w;
}

// ============================================================
// Stage 1: u = features @ kernel
// ============================================================
__global__ __launch_bounds__(256) void k_gemmA(const float* __restrict__ feat,
                                               const float* __restrict__ W) {
    __shared__ float fs[16][DD];
    int tid = threadIdx.x;
    int r0  = blockIdx.x * 16;
    for (int idx = tid; idx < 16 * DD; idx += 256)
        fs[idx >> 8][idx & 255] = feat[(size_t)(r0 + (idx >> 8)) * DD + (idx & 255)];
    __syncthreads();
    int col = tid & 127, rg = tid >> 7;
    float acc[8] = {0.f,0.f,0.f,0.f,0.f,0.f,0.f,0.f};
    for (int d = 0; d < DD; d++) {
        float kv = W[d * UU + col];
        #pragma unroll
        for (int r = 0; r < 8; r++)
            acc[r] = fmaf(fs[rg * 8 + r][d], kv, acc[r]);
    }
    #pragma unroll
    for (int r = 0; r < 8; r++)
        g_buf[(size_t)(r0 + rg * 8 + r) * UU + col] = acc[r];
}

// ============================================================
// Stage 2: x = expmap0(u); emit fp16 split, bf16 transposed split, x2
// ============================================================
__global__ __launch_bounds__(128) void k_expmap() {
    __shared__ float sm[4];
    int row = blockIdx.x, t = threadIdx.x;
    float v  = g_buf[(size_t)row * UU + t];
    float n2 = blockReduce128(v * v, sm);
    float n  = fmaxf(sqrtf(n2), 1e-15f);
    float xv = tanhf(n) / n * v;

    __half hh = __float2half(xv);
    __half hl = __float2half(xv - __half2float(hh));
    g_xh[(size_t)row * UU + t] = hh;
    g_xl[(size_t)row * UU + t] = hl;

    __nv_bfloat16 bh = __float2bfloat16(xv);
    __nv_bfloat16 bl = __float2bfloat16(xv - __bfloat162float(bh));
    g_xTh[(size_t)t * NN + row] = bh;
    g_xTl[(size_t)t * NN + row] = bl;

    float s2 = blockReduce128(xv * xv, sm);
    if (t == 0) g_x2[row] = s2;
}

// ============================================================
// Stage 3 (k_attn): S = Xi . Xj^T via fp16-split HMMA, fused score epilogue.
// grid 4096 (64 ib x 64 jb), 256 threads (8 warps of m32 x n64).
// smem: Ai hi/lo + Bj hi/lo fp16 tiles (stride-padded); S f32 aliases A.
// ============================================================
#define SKA 136
#define ATILE (128 * SKA * 2)      /* 34816 B per fp16 tile */
#define G1_SMEM (4 * ATILE)        /* 139264 B */
#define SKS 132

__global__ __launch_bounds__(256) void k_attn(const int* __restrict__ adj) {
    extern __shared__ char smc[];
    uint32_t sb = smem_to_u32(smc);
    int tid = threadIdx.x, wid = tid >> 5, lane = tid & 31;
    int jb = blockIdx.x & 63, ib = blockIdx.x >> 6;
    int i0 = ib * 128, j0 = jb * 128;

    // ---- load 4 fp16 tiles (Ai hi/lo at i0, Bj hi/lo at j0) ----
    #pragma unroll
    for (int t4 = 0; t4 < 4; t4++) {
        const __half* src = (t4 & 1) ? g_xl : g_xh;
        int r0 = (t4 < 2) ? i0 : j0;
        char* dst = smc + t4 * ATILE;
        #pragma unroll
        for (int it = 0; it < 8; it++) {
            int idx = it * 256 + tid;
            int row = idx >> 4, q = idx & 15;
            uint4 v = ((const uint4*)(src + (size_t)(r0 + row) * UU))[q];
            *(uint4*)(dst + (row * SKA + q * 8) * 2) = v;
        }
    }
    __syncthreads();

    int wm = (wid & 3) * 32, wn = (wid >> 2) * 64;
    int aRow = (lane & 7) + ((lane >> 3) & 1) * 8;
    int aCol = (lane >> 4) * 8;
    int bRow = (lane & 7) + (lane >> 4) * 8;
    int bCol = ((lane >> 3) & 1) * 8;

    float acc[2][8][4];
    #pragma unroll
    for (int mi = 0; mi < 2; mi++)
        #pragma unroll
        for (int nb = 0; nb < 8; nb++)
            #pragma unroll
            for (int q = 0; q < 4; q++) acc[mi][nb][q] = 0.f;

    // ---- 3 products: Ai_hi*Bj_hi + Ai_hi*Bj_lo + Ai_lo*Bj_hi ----
    #pragma unroll
    for (int p = 0; p < 3; p++) {
        uint32_t Ab = sb + (p == 2 ? ATILE : 0);
        uint32_t Bb = sb + (p == 1 ? 3 * ATILE : 2 * ATILE);
        #pragma unroll
        for (int ksv = 0; ksv < 8; ksv++) {
            int k0 = ksv * 16;
            uint32_t a[2][4], b[4][4];
            #pragma unroll
            for (int mi = 0; mi < 2; mi++)
                ldsm4(a[mi][0], a[mi][1], a[mi][2], a[mi][3],
                      Ab + (uint32_t)((wm + mi * 16 + aRow) * SKA + k0 + aCol) * 2);
            #pragma unroll
            for (int nb = 0; nb < 4; nb++)
                ldsm4(b[nb][0], b[nb][1], b[nb][2], b[nb][3],
                      Bb + (uint32_t)((wn + nb * 16 + bRow) * SKA + k0 + bCol) * 2);
            #pragma unroll
            for (int mi = 0; mi < 2; mi++)
                #pragma unroll
                for (int nb = 0; nb < 4; nb++) {
                    mma_f16(acc[mi][2 * nb],     a[mi], b[nb][0], b[nb][1]);
                    mma_f16(acc[mi][2 * nb + 1], a[mi], b[nb][2], b[nb][3]);
                }
        }
    }
    __syncthreads();

    // ---- stage S[i][j] into smem (aliases A-tile region) ----
    float* S = (float*)smc;
    int g = lane >> 2, tq = lane & 3;
    #pragma unroll
    for (int mi = 0; mi < 2; mi++)
        #pragma unroll
        for (int nbi = 0; nbi < 8; nbi++) {
            int r = wm + mi * 16 + g, c = wn + nbi * 8 + 2 * tq;
            *(float2*)&S[r * SKS + c] =
                make_float2(acc[mi][nbi][0], acc[mi][nbi][1]);
            *(float2*)&S[(r + 8) * SKS + c] =
                make_float2(acc[mi][nbi][2], acc[mi][nbi][3]);
        }
    __syncthreads();

    // ---- score epilogue: warp w handles i = w*16..w*16+15, lanes = j ----
    float x2j[4];
    #pragma unroll
    for (int s4 = 0; s4 < 4; s4++) x2j[s4] = g_x2[j0 + s4 * 32 + lane];

    #pragma unroll 1
    for (int ii = 0; ii < 16; ii++) {
        int il = wid * 16 + ii, ig = i0 + il;
        float x2i = g_x2[ig];
        float rsum = 0.f;
        #pragma unroll
        for (int s4 = 0; s4 < 4; s4++) {
            int j = s4 * 32 + lane;
            float xy = S[il * SKS + j];
            int am = adj[(size_t)ig * NN + j0 + j];
            float w = score_w(xy, x2i, x2j[s4], am);
            __nv_bfloat16 bh = __float2bfloat16(w);
            __nv_bfloat16 bl = __float2bfloat16(w - __bfloat162float(bh));
            g_w[(size_t)ig * NN + j0 + j] =
                (unsigned)__bfloat16_as_ushort(bh) |
                ((unsigned)__bfloat16_as_ushort(bl) << 16);
            rsum += w;
        }
        #pragma unroll
        for (int o = 16; o > 0; o >>= 1)
            rsum += __shfl_xor_sync(0xffffffffu, rsum, o);
        if (lane == 0) g_rsump[ig * 64 + jb] = rsum;
    }
}

// ============================================================
// Stage 4 (k_agg): mx = W @ X via bf16-split HMMA.
// grid 128 (64 i-tiles x ksplit 2), 256 threads, 64-j chunks, double buffer.
// ============================================================
#define SKC 72
#define CT  (128 * SKC * 2)        /* 18432 B per bf16 chunk tile */
#define STG (4 * CT)               /* 73728 B per stage */
#define G2_SMEM (2 * STG)          /* 147456 B */

__global__ __launch_bounds__(256) void k_agg() {
    extern __shared__ char smc[];
    uint32_t sb = smem_to_u32(smc);
    int tid = threadIdx.x, wid = tid >> 5, lane = tid & 31;
    int ib = blockIdx.x >> 1, ks = blockIdx.x & 1;
    int i0 = ib * 128, jbeg = ks * 4096;

    int wm = (wid & 3) * 32, wn = (wid >> 2) * 64;
    int aRow = (lane & 7) + ((lane >> 3) & 1) * 8;
    int aCol = (lane >> 4) * 8;
    int bRow = (lane & 7) + (lane >> 4) * 8;
    int bCol = ((lane >> 3) & 1) * 8;

    float acc[2][8][4];
    #pragma unroll
    for (int mi = 0; mi < 2; mi++)
        #pragma unroll
        for (int nb = 0; nb < 8; nb++)
            #pragma unroll
            for (int q = 0; q < 4; q++) acc[mi][nb][q] = 0.f;

    // ---- chunk loader (W packed -> hi/lo tiles; X^T hi/lo tiles) ----
    #define LOAD_CHUNK(cc, ss) do {                                            \
        int jc0 = jbeg + (cc) * 64;                                            \
        char* st = smc + (ss) * STG;                                           \
        _Pragma("unroll")                                                      \
        for (int it = 0; it < 8; it++) {                                       \
            int idx = it * 256 + tid;                                          \
            int row = idx >> 4, q = idx & 15;                                  \
            uint4 v = *(const uint4*)(g_w + (size_t)(i0 + row) * NN + jc0 + q * 4); \
            unsigned h01 = __byte_perm(v.x, v.y, 0x5410);                      \
            unsigned h23 = __byte_perm(v.z, v.w, 0x5410);                      \
            unsigned l01 = __byte_perm(v.x, v.y, 0x7632);                      \
            unsigned l23 = __byte_perm(v.z, v.w, 0x7632);                      \
            int off = (row * SKC + q * 4) * 2;                                 \
            *(uint2*)(st + off)      = make_uint2(h01, h23);                   \
            *(uint2*)(st + CT + off) = make_uint2(l01, l23);                   \
        }                                                                      \
        _Pragma("unroll")                                                      \
        for (int it = 0; it < 4; it++) {                                       \
            int idx = it * 256 + tid;                                          \
            int row = idx >> 3, q = idx & 7;                                   \
            int off = (row * SKC + q * 8) * 2;                                 \
            uint4 vh = ((const uint4*)(g_xTh + (size_t)row * NN + jc0))[q];    \
            *(uint4*)(st + 2 * CT + off) = vh;                                 \
            uint4 vl = ((const uint4*)(g_xTl + (size_t)row * NN + jc0))[q];    \
            *(uint4*)(st + 3 * CT + off) = vl;                                 \
        }                                                                      \
    } while (0)

    LOAD_CHUNK(0, 0);
    __syncthreads();

    for (int c = 0; c < 64; c++) {
        int s = c & 1;
        if (c + 1 < 64) LOAD_CHUNK(c + 1, s ^ 1);

        uint32_t stb = sb + s * STG;
        #pragma unroll
        for (int p = 0; p < 3; p++) {
            uint32_t Ab = stb + (p == 2 ? CT : 0);            // W: hi, hi, lo
            uint32_t Bb = stb + 2 * CT + (p == 1 ? CT : 0);   // X: hi, lo, hi
            #pragma unroll
            for (int ksv = 0; ksv < 4; ksv++) {
                int k0 = ksv * 16;
                uint32_t a[2][4], b[4][4];
                #pragma unroll
                for (int mi = 0; mi < 2; mi++)
                    ldsm4(a[mi][0], a[mi][1], a[mi][2], a[mi][3],
                          Ab + (uint32_t)((wm + mi * 16 + aRow) * SKC + k0 + aCol) * 2);
                #pragma unroll
                for (int nb = 0; nb < 4; nb++)
                    ldsm4(b[nb][0], b[nb][1], b[nb][2], b[nb][3],
                          Bb + (uint32_t)((wn + nb * 16 + bRow) * SKC + k0 + bCol) * 2);
                #pragma unroll
                for (int mi = 0; mi < 2; mi++)
                    #pragma unroll
                    for (int nb = 0; nb < 4; nb++) {
                        mma_bf16(acc[mi][2 * nb],     a[mi], b[nb][0], b[nb][1]);
                        mma_bf16(acc[mi][2 * nb + 1], a[mi], b[nb][2], b[nb][3]);
                    }
            }
        }
        __syncthreads();
    }

    // ---- writeback (each (i,d) owned by exactly one CTA per ksplit half) ----
    int g = lane >> 2, tq = lane & 3;
    #pragma unroll
    for (int mi = 0; mi < 2; mi++)
        #pragma unroll
        for (int nbi = 0; nbi < 8; nbi++) {
            int irow = i0 + wm + mi * 16 + g;
            int dcol = wn + nbi * 8 + 2 * tq;
            *(float2*)&g_mx2[((size_t)ks * NN + irow) * UU + dcol] =
                make_float2(acc[mi][nbi][0], acc[mi][nbi][1]);
            *(float2*)&g_mx2[((size_t)ks * NN + irow + 8) * UU + dcol] =
                make_float2(acc[mi][nbi][2], acc[mi][nbi][3]);
        }
}

// ============================================================
// Stage 5: combine halves, normalize, hyperbolic rescale + mobius bias add
// ============================================================
__global__ __launch_bounds__(128) void k_epilogue(const float* __restrict__ bias,
                                                  float* __restrict__ out) {
    __shared__ float sm[4];
    int row = blockIdx.x, t = threadIdx.x;

    float rp = (t < 64) ? g_rsump[row * 64 + t] : 0.f;
    float rs = blockReduce128(rp, sm);

    float m = (g_mx2[(size_t)row * UU + t] +
               g_mx2[(size_t)(NN + row) * UU + t]) / rs;
    float mn2 = blockReduce128(m * m, sm);
    float x2i = g_x2[row];
    float x_n  = fmaxf(sqrtf(x2i), 1e-15f);
    float mx_n = fmaxf(sqrtf(mn2), 1e-15f);
    float xa   = fminf(x_n, 1.f - 1e-7f);
    float art  = 0.5f * (log1pf(xa) - log1pf(-xa));
    float alpha = tanhf(mx_n / x_n * art) / mx_n;
    float ov = alpha * m;

    float bv  = bias[t];
    float bn2 = blockReduce128(bv * bv, sm);
    float bn  = fmaxf(sqrtf(bn2), 1e-15f);
    float bvx = tanhf(bn) / bn * bv;

    float y2  = blockReduce128(bvx * bvx, sm);
    float xy  = blockReduce128(ov * bvx, sm);
    float x2o = blockReduce128(ov * ov, sm);
    float cx  = 1.f + 2.f * xy + y2;
    float cy  = 1.f - x2o;
    float den = fmaxf(fmaf(x2o, y2, 1.f + 2.f * xy), 1e-15f);
    out[(size_t)row * UU + t] = (cx * ov + cy * bvx) / den;
}

// ============================================================
extern "C" void kernel_launch(void* const* d_in, const int* in_sizes, int n_in,
                              void* d_out, int out_size) {
    const float* feat = (const float*)d_in[0];
    const int*   adj  = (const int*)  d_in[1];
    const float* W    = (const float*)d_in[2];
    const float* bias = (const float*)d_in[3];
    float* out = (float*)d_out;

    cudaFuncSetAttribute(k_attn, cudaFuncAttributeMaxDynamicSharedMemorySize, G1_SMEM);
    cudaFuncSetAttribute(k_agg,  cudaFuncAttributeMaxDynamicSharedMemorySize, G2_SMEM);

    k_gemmA   <<<NN / 16, 256>>>(feat, W);
    k_expmap  <<<NN, 128>>>();
    k_attn    <<<64 * 64, 256, G1_SMEM>>>(adj);
    k_agg     <<<128, 256, G2_SMEM>>>();
    k_epilogue<<<NN, 128>>>(bias, out);
}

// round 5
// speedup vs baseline: 2.8101x; 1.4679x over previous
#include <cuda_runtime.h>
#include <cuda_bf16.h>
#include <cuda_fp16.h>
#include <cstdint>
#include <math.h>

#define NN 8192
#define DD 256
#define UU 128

// ================= device scratch (no allocations allowed) =================
__device__ __align__(256) float          g_buf[NN * UU];     // stage1: u = feat@W
__device__ __align__(256) __half         g_xh[NN * UU];      // fp16 split of x (node-major)
__device__ __align__(256) __half         g_xl[NN * UU];
__device__ __align__(256) __nv_bfloat16  g_xTh[UU * NN];     // bf16 split of x, transposed
__device__ __align__(256) __nv_bfloat16  g_xTl[UU * NN];
__device__ __align__(256) float          g_x2[NN];
__device__ __align__(256) unsigned int   g_w[(size_t)NN * NN];   // packed (w_hi | w_lo<<16) bf16
__device__ __align__(256) uint32_t       g_adjb[(size_t)NN * NN / 32]; // adjacency bitmask
__device__ __align__(256) float          g_rsump[NN * 8];         // per (i, j-quarter) sums
__device__ __align__(256) float          g_mx2[2 * NN * UU];      // ksplit halves of mx

// ======================= helpers =======================
__device__ __forceinline__ uint32_t smem_to_u32(const void* p) {
    uint32_t a;
    asm("{ .reg .u64 t; cvta.to.shared.u64 t, %1; cvt.u32.u64 %0, t; }"
        : "=r"(a) : "l"(p));
    return a;
}
__device__ __forceinline__ void cp16(uint32_t saddr, const void* gaddr) {
    asm volatile("cp.async.cg.shared.global [%0], [%1], 16;"
                 :: "r"(saddr), "l"(gaddr));
}
#define CP_COMMIT() asm volatile("cp.async.commit_group;" ::: "memory")
#define CP_WAIT0()  asm volatile("cp.async.wait_group 0;" ::: "memory")

__device__ __forceinline__ void ldsm4(uint32_t& r0, uint32_t& r1, uint32_t& r2,
                                      uint32_t& r3, uint32_t addr) {
    asm volatile("ldmatrix.sync.aligned.m8n8.x4.shared.b16 {%0,%1,%2,%3}, [%4];"
                 : "=r"(r0), "=r"(r1), "=r"(r2), "=r"(r3) : "r"(addr));
}
__device__ __forceinline__ void mma_f16(float* d, const uint32_t* a,
                                        uint32_t b0, uint32_t b1) {
    asm volatile("mma.sync.aligned.m16n8k16.row.col.f32.f16.f16.f32 "
                 "{%0,%1,%2,%3}, {%4,%5,%6,%7}, {%8,%9}, {%0,%1,%2,%3};"
                 : "+f"(d[0]), "+f"(d[1]), "+f"(d[2]), "+f"(d[3])
                 : "r"(a[0]), "r"(a[1]), "r"(a[2]), "r"(a[3]), "r"(b0), "r"(b1));
}
__device__ __forceinline__ void mma_bf16(float* d, const uint32_t* a,
                                         uint32_t b0, uint32_t b1) {
    asm volatile("mma.sync.aligned.m16n8k16.row.col.f32.bf16.bf16.f32 "
                 "{%0,%1,%2,%3}, {%4,%5,%6,%7}, {%8,%9}, {%0,%1,%2,%3};"
                 : "+f"(d[0]), "+f"(d[1]), "+f"(d[2]), "+f"(d[3])
                 : "r"(a[0]), "r"(a[1]), "r"(a[2]), "r"(a[3]), "r"(b0), "r"(b1));
}

__device__ __forceinline__ float blockReduce128(float v, volatile float* sm) {
    #pragma unroll
    for (int o = 16; o > 0; o >>= 1) v += __shfl_xor_sync(0xffffffffu, v, o);
    if ((threadIdx.x & 31) == 0) sm[threadIdx.x >> 5] = v;
    __syncthreads();
    float r = sm[0] + sm[1] + sm[2] + sm[3];
    __syncthreads();
    return r;
}

// w = exp(hyperbolic distance), closed form; masked by adjacency / dist==0
__device__ __forceinline__ float score_w(float xy, float x2i, float x2j, int am) {
    float A = 1.f - 2.f * xy + x2j;
    float B = 1.f - x2i;
    float num = fmaf(A * A, x2i, fmaf(-2.f * A * B, xy, B * B * x2j));
    num = fmaxf(num, 0.f);
    float den = fmaxf(fmaf(x2i, x2j, 1.f - 2.f * xy), 1e-15f);
    float sq  = sqrtf(num);
    float w;
    if (sq < (1.f - 1e-7f) * den) w = (den + sq) / (den - sq);
    else                          w = (2.f - 1e-7f) / 1e-7f;
    if (am == 0 || !(sq > 0.f)) w = 0.f;
    return w;
}
__device__ __forceinline__ unsigned pack_w(float w) {
    __nv_bfloat16 bh = __float2bfloat16(w);
    __nv_bfloat16 bl = __float2bfloat16(w - __bfloat162float(bh));
    return (unsigned)__bfloat16_as_ushort(bh) |
           ((unsigned)__bfloat16_as_ushort(bl) << 16);
}

// ============================================================
// Stage 0: adjacency -> bitmask (1 thread per 32 ints)
// ============================================================
__global__ __launch_bounds__(256) void k_adjmask(const int* __restrict__ adj) {
    size_t w = (size_t)blockIdx.x * 256 + threadIdx.x;
    const int4* p = (const int4*)(adj + w * 32);
    uint32_t m = 0;
    #pragma unroll
    for (int q = 0; q < 8; q++) {
        int4 v = p[q];
        m |= (v.x != 0 ? 1u : 0u) << (q * 4 + 0);
        m |= (v.y != 0 ? 1u : 0u) << (q * 4 + 1);
        m |= (v.z != 0 ? 1u : 0u) << (q * 4 + 2);
        m |= (v.w != 0 ? 1u : 0u) << (q * 4 + 3);
    }
    g_adjb[w] = m;
}

// ============================================================
// Stage 1: u = features @ kernel
// ============================================================
__global__ __launch_bounds__(256) void k_gemmA(const float* __restrict__ feat,
                                               const float* __restrict__ W) {
    __shared__ float fs[16][DD];
    int tid = threadIdx.x;
    int r0  = blockIdx.x * 16;
    for (int idx = tid; idx < 16 * DD; idx += 256)
        fs[idx >> 8][idx & 255] = feat[(size_t)(r0 + (idx >> 8)) * DD + (idx & 255)];
    __syncthreads();
    int col = tid & 127, rg = tid >> 7;
    float acc[8] = {0.f,0.f,0.f,0.f,0.f,0.f,0.f,0.f};
    for (int d = 0; d < DD; d++) {
        float kv = W[d * UU + col];
        #pragma unroll
        for (int r = 0; r < 8; r++)
            acc[r] = fmaf(fs[rg * 8 + r][d], kv, acc[r]);
    }
    #pragma unroll
    for (int r = 0; r < 8; r++)
        g_buf[(size_t)(r0 + rg * 8 + r) * UU + col] = acc[r];
}

// ============================================================
// Stage 2: x = expmap0(u); fp16 split, bf16 transposed split, x2
// ============================================================
__global__ __launch_bounds__(128) void k_expmap() {
    __shared__ float sm[4];
    int row = blockIdx.x, t = threadIdx.x;
    float v  = g_buf[(size_t)row * UU + t];
    float n2 = blockReduce128(v * v, sm);
    float n  = fmaxf(sqrtf(n2), 1e-15f);
    float xv = tanhf(n) / n * v;

    __half hh = __float2half(xv);
    __half hl = __float2half(xv - __half2float(hh));
    g_xh[(size_t)row * UU + t] = hh;
    g_xl[(size_t)row * UU + t] = hl;

    __nv_bfloat16 bh = __float2bfloat16(xv);
    __nv_bfloat16 bl = __float2bfloat16(xv - __bfloat162float(bh));
    g_xTh[(size_t)t * NN + row] = bh;
    g_xTl[(size_t)t * NN + row] = bl;

    float s2 = blockReduce128(xv * xv, sm);
    if (t == 0) g_x2[row] = s2;
}

// ============================================================
// Stage 3 (k_attn): persistent, cp.async double-buffered.
// grid 512 = 64 ib x 8 jq; each CTA: A(i) resident, loops 8 j-tiles.
// smem: [Ahi][Alo][Bhi0][Blo0][Bhi1][Blo1] + rsum combine area.
// ============================================================
#define SKA 136
#define ATILE (128 * SKA * 2)          /* 34816 B */
#define RS_OFF (6 * ATILE)
#define G1_SMEM (6 * ATILE + 1024)

__device__ __forceinline__ void cp_tile16(char* dst, const __half* src,
                                          int r0, int tid) {
    #pragma unroll
    for (int it = 0; it < 8; it++) {
        int idx = it * 256 + tid;
        int row = idx >> 4, q = idx & 15;
        cp16(smem_to_u32(dst + (row * SKA + q * 8) * 2),
             (const void*)(src + (size_t)(r0 + row) * UU + q * 8));
    }
}

__global__ __launch_bounds__(256) void k_attn() {
    extern __shared__ char smc[];
    uint32_t sb = smem_to_u32(smc);
    int tid = threadIdx.x, wid = tid >> 5, lane = tid & 31;
    int ib = blockIdx.x >> 3, jq = blockIdx.x & 7;
    int i0 = ib * 128;

    int wm = (wid & 3) * 32, wn = (wid >> 2) * 64;
    int g = lane >> 2, tq = lane & 3;
    int aRow = (lane & 7) + ((lane >> 3) & 1) * 8;
    int aCol = (lane >> 4) * 8;
    int bRow = (lane & 7) + (lane >> 4) * 8;
    int bCol = ((lane >> 3) & 1) * 8;

    // prologue: A hi/lo resident + B(c=0) hi/lo
    cp_tile16(smc + 0 * ATILE, g_xh, i0, tid);
    cp_tile16(smc + 1 * ATILE, g_xl, i0, tid);
    cp_tile16(smc + 2 * ATILE, g_xh, jq * 1024, tid);
    cp_tile16(smc + 3 * ATILE, g_xl, jq * 1024, tid);
    CP_COMMIT();

    // per-thread row norms (4 rows owned across mma tiles)
    float x2i[4];
    #pragma unroll
    for (int mi = 0; mi < 2; mi++)
        #pragma unroll
        for (int rh = 0; rh < 2; rh++)
            x2i[mi * 2 + rh] = g_x2[i0 + wm + mi * 16 + g + rh * 8];

    float rsum[4] = {0.f, 0.f, 0.f, 0.f};

    CP_WAIT0();
    __syncthreads();

    for (int c = 0; c < 8; c++) {
        int s = c & 1;
        if (c < 7) {   // prefetch next j-tile into the other stage
            int jn = jq * 1024 + (c + 1) * 128;
            cp_tile16(smc + (2 + 2 * (s ^ 1)) * ATILE, g_xh, jn, tid);
            cp_tile16(smc + (3 + 2 * (s ^ 1)) * ATILE, g_xl, jn, tid);
            CP_COMMIT();
        }

        // ---- MMA: 3 products (hi*hi + hi*lo + lo*hi) ----
        float acc[2][8][4];
        #pragma unroll
        for (int mi = 0; mi < 2; mi++)
            #pragma unroll
            for (int nb = 0; nb < 8; nb++)
                #pragma unroll
                for (int q = 0; q < 4; q++) acc[mi][nb][q] = 0.f;

        #pragma unroll
        for (int p = 0; p < 3; p++) {
            uint32_t Ab = sb + (p == 2 ? ATILE : 0);
            uint32_t Bb = sb + (uint32_t)(2 + 2 * s + (p == 1 ? 1 : 0)) * ATILE;
            #pragma unroll
            for (int ksv = 0; ksv < 8; ksv++) {
                int k0 = ksv * 16;
                uint32_t a[2][4], b[4][4];
                #pragma unroll
                for (int mi = 0; mi < 2; mi++)
                    ldsm4(a[mi][0], a[mi][1], a[mi][2], a[mi][3],
                          Ab + (uint32_t)((wm + mi * 16 + aRow) * SKA + k0 + aCol) * 2);
                #pragma unroll
                for (int nb = 0; nb < 4; nb++)
                    ldsm4(b[nb][0], b[nb][1], b[nb][2], b[nb][3],
                          Bb + (uint32_t)((wn + nb * 16 + bRow) * SKA + k0 + bCol) * 2);
                #pragma unroll
                for (int mi = 0; mi < 2; mi++)
                    #pragma unroll
                    for (int nb = 0; nb < 4; nb++) {
                        mma_f16(acc[mi][2 * nb],     a[mi], b[nb][0], b[nb][1]);
                        mma_f16(acc[mi][2 * nb + 1], a[mi], b[nb][2], b[nb][3]);
                    }
            }
        }

        // ---- score epilogue straight from accumulators ----
        int j0c = jq * 1024 + c * 128;
        #pragma unroll
        for (int mi = 0; mi < 2; mi++)
            #pragma unroll
            for (int rh = 0; rh < 2; rh++) {
                int ig = i0 + wm + mi * 16 + g + rh * 8;
                uint2 mwv = *(const uint2*)&g_adjb[(size_t)ig * (NN / 32)
                                                   + ((j0c + wn) >> 5)];
                float x2iv = x2i[mi * 2 + rh];
                float rs = 0.f;
                #pragma unroll
                for (int nbi = 0; nbi < 8; nbi++) {
                    int jl = wn + nbi * 8 + 2 * tq;
                    int jg = j0c + jl;
                    float2 x2jv = *(const float2*)&g_x2[jg];
                    uint32_t mword = (nbi < 4) ? mwv.x : mwv.y;
                    int sh = jl & 31;
                    int a0 = (mword >> sh) & 1;
                    int a1 = (mword >> (sh + 1)) & 1;
                    float w0 = score_w(acc[mi][nbi][rh * 2 + 0], x2iv, x2jv.x, a0);
                    float w1 = score_w(acc[mi][nbi][rh * 2 + 1], x2iv, x2jv.y, a1);
                    *(uint2*)&g_w[(size_t)ig * NN + jg] =
                        make_uint2(pack_w(w0), pack_w(w1));
                    rs += w0 + w1;
                }
                rsum[mi * 2 + rh] += rs;
            }

        if (c < 7) CP_WAIT0();
        __syncthreads();
    }

    // ---- row-sum combine: reduce over tq, then warp pairs ----
    #pragma unroll
    for (int r = 0; r < 4; r++) {
        rsum[r] += __shfl_xor_sync(0xffffffffu, rsum[r], 1);
        rsum[r] += __shfl_xor_sync(0xffffffffu, rsum[r], 2);
    }
    float* RS = (float*)(smc + RS_OFF);    // [8 warps][32 rows-in-band]
    if (tq == 0) {
        RS[wid * 32 +  0 + g] = rsum[0];
        RS[wid * 32 +  8 + g] = rsum[1];
        RS[wid * 32 + 16 + g] = rsum[2];
        RS[wid * 32 + 24 + g] = rsum[3];
    }
    __syncthreads();
    if (wid < 4) {
        float v = RS[wid * 32 + lane] + RS[(wid + 4) * 32 + lane];
        g_rsump[(i0 + wid * 32 + lane) * 8 + jq] = v;
    }
}

// ============================================================
// Stage 4 (k_agg): mx = W @ X, bf16-split HMMA, cp.async X + reg-prefetched W.
// grid 128 (64 i-tiles x ksplit 2), 64-j chunks, double buffer.
// stage layout: [Whi][Wlo][Xhi][Xlo], each 128 x SKC bf16.
// ============================================================
#define SKC 72
#define CT  (128 * SKC * 2)        /* 18432 B */
#define STG (4 * CT)               /* 73728 B */
#define G2_SMEM (2 * STG)          /* 147456 B */

__global__ __launch_bounds__(256) void k_agg() {
    extern __shared__ char smc[];
    uint32_t sb = smem_to_u32(smc);
    int tid = threadIdx.x, wid = tid >> 5, lane = tid & 31;
    int ib = blockIdx.x >> 1, ks = blockIdx.x & 1;
    int i0 = ib * 128, jbeg = ks * 4096;

    int wm = (wid & 3) * 32, wn = (wid >> 2) * 64;
    int aRow = (lane & 7) + ((lane >> 3) & 1) * 8;
    int aCol = (lane >> 4) * 8;
    int bRow = (lane & 7) + (lane >> 4) * 8;
    int bCol = ((lane >> 3) & 1) * 8;

    int wrow = tid >> 1, wq2 = tid & 1;      // W: 2 threads per row, 8 u32 each? (see below)

    float acc[2][8][4];
    #pragma unroll
    for (int mi = 0; mi < 2; mi++)
        #pragma unroll
        for (int nb = 0; nb < 8; nb++)
            #pragma unroll
            for (int q = 0; q < 4; q++) acc[mi][nb][q] = 0.f;

    // ---- X^T cp.async loader ----
    #define CP_X(cc, ss) do {                                                  \
        int jc0 = jbeg + (cc) * 64;                                            \
        char* st = smc + (ss) * STG;                                           \
        _Pragma("unroll")                                                      \
        for (int it = 0; it < 4; it++) {                                       \
            int idx = it * 256 + tid;                                          \
            int row = idx >> 3, q = idx & 7;                                   \
            int off = (row * SKC + q * 8) * 2;                                 \
            cp16(smem_to_u32(st + 2 * CT + off),                               \
                 (const void*)(g_xTh + (size_t)row * NN + jc0 + q * 8));       \
            cp16(smem_to_u32(st + 3 * CT + off),                               \
                 (const void*)(g_xTl + (size_t)row * NN + jc0 + q * 8));       \
        }                                                                      \
    } while (0)

    // ---- W loaders: LDG to regs / perm+STS from regs ----
    #define LDG_W(cc, vreg) do {                                               \
        int jc0 = jbeg + (cc) * 64;                                            \
        _Pragma("unroll")                                                      \
        for (int it = 0; it < 8; it++) {                                       \
            int idx = it * 256 + tid;                                          \
            int row = idx >> 4, q = idx & 15;                                  \
            (vreg)[it] = *(const uint4*)(g_w + (size_t)(i0 + row) * NN         \
                                         + jc0 + q * 4);                       \
        }                                                                      \
    } while (0)
    #define STS_W(ss, vreg) do {                                               \
        char* st = smc + (ss) * STG;                                           \
        _Pragma("unroll")                                                      \
        for (int it = 0; it < 8; it++) {                                       \
            int idx = it * 256 + tid;                                          \
            int row = idx >> 4, q = idx & 15;                                  \
            unsigned h01 = __byte_perm((vreg)[it].x, (vreg)[it].y, 0x5410);    \
            unsigned h23 = __byte_perm((vreg)[it].z, (vreg)[it].w, 0x5410);    \
            unsigned l01 = __byte_perm((vreg)[it].x, (vreg)[it].y, 0x7632);    \
            unsigned l23 = __byte_perm((vreg)[it].z, (vreg)[it].w, 0x7632);    \
            int off = (row * SKC + q * 4) * 2;                                 \
            *(uint2*)(st + off)      = make_uint2(h01, h23);                   \
            *(uint2*)(st + CT + off) = make_uint2(l01, l23);                   \
        }                                                                      \
    } while (0)

    // prologue: chunk 0
    uint4 vW[8];
    CP_X(0, 0);
    CP_COMMIT();
    LDG_W(0, vW);
    STS_W(0, vW);
    CP_WAIT0();
    __syncthreads();

    for (int c = 0; c < 64; c++) {
        int s = c & 1;
        if (c < 63) {
            CP_X(c + 1, s ^ 1);
            CP_COMMIT();
            LDG_W(c + 1, vW);     // LDG latency hidden behind MMAs below
        }

        uint32_t stb = sb + s * STG;
        #pragma unroll
        for (int p = 0; p < 3; p++) {
            uint32_t Ab = stb + (p == 2 ? CT : 0);            // W: hi, hi, lo
            uint32_t Bb = stb + 2 * CT + (p == 1 ? CT : 0);   // X: hi, lo, hi
            #pragma unroll
            for (int ksv = 0; ksv < 4; ksv++) {
                int k0 = ksv * 16;
                uint32_t a[2][4], b[4][4];
                #pragma unroll
                for (int mi = 0; mi < 2; mi++)
                    ldsm4(a[mi][0], a[mi][1], a[mi][2], a[mi][3],
                          Ab + (uint32_t)((wm + mi * 16 + aRow) * SKC + k0 + aCol) * 2);
                #pragma unroll
                for (int nb = 0; nb < 4; nb++)
                    ldsm4(b[nb][0], b[nb][1], b[nb][2], b[nb][3],
                          Bb + (uint32_t)((wn + nb * 16 + bRow) * SKC + k0 + bCol) * 2);
                #pragma unroll
                for (int mi = 0; mi < 2; mi++)
                    #pragma unroll
                    for (int nb = 0; nb < 4; nb++) {
                        mma_bf16(acc[mi][2 * nb],     a[mi], b[nb][0], b[nb][1]);
                        mma_bf16(acc[mi][2 * nb + 1], a[mi], b[nb][2], b[nb][3]);
                    }
            }
        }

        if (c < 63) STS_W(s ^ 1, vW);
        CP_WAIT0();
        __syncthreads();
    }

    // ---- writeback ----
    int g = lane >> 2, tq = lane & 3;
    #pragma unroll
    for (int mi = 0; mi < 2; mi++)
        #pragma unroll
        for (int nbi = 0; nbi < 8; nbi++) {
            int irow = i0 + wm + mi * 16 + g;
            int dcol = wn + nbi * 8 + 2 * tq;
            *(float2*)&g_mx2[((size_t)ks * NN + irow) * UU + dcol] =
                make_float2(acc[mi][nbi][0], acc[mi][nbi][1]);
            *(float2*)&g_mx2[((size_t)ks * NN + irow + 8) * UU + dcol] =
                make_float2(acc[mi][nbi][2], acc[mi][nbi][3]);
        }
    (void)wrow; (void)wq2;
}

// ============================================================
// Stage 5: combine halves, normalize, hyperbolic rescale + mobius bias add
// ============================================================
__global__ __launch_bounds__(128) void k_epilogue(const float* __restrict__ bias,
                                                  float* __restrict__ out) {
    __shared__ float sm[4];
    int row = blockIdx.x, t = threadIdx.x;

    float rp = (t < 8) ? g_rsump[row * 8 + t] : 0.f;
    float rs = blockReduce128(rp, sm);

    float m = (g_mx2[(size_t)row * UU + t] +
               g_mx2[(size_t)(NN + row) * UU + t]) / rs;
    float mn2 = blockReduce128(m * m, sm);
    float x2i = g_x2[row];
    float x_n  = fmaxf(sqrtf(x2i), 1e-15f);
    float mx_n = fmaxf(sqrtf(mn2), 1e-15f);
    float xa   = fminf(x_n, 1.f - 1e-7f);
    float art  = 0.5f * (log1pf(xa) - log1pf(-xa));
    float alpha = tanhf(mx_n / x_n * art) / mx_n;
    float ov = alpha * m;

    float bv  = bias[t];
    float bn2 = blockReduce128(bv * bv, sm);
    float bn  = fmaxf(sqrtf(bn2), 1e-15f);
    float bvx = tanhf(bn) / bn * bv;

    float y2  = blockReduce128(bvx * bvx, sm);
    float xy  = blockReduce128(ov * bvx, sm);
    float x2o = blockReduce128(ov * ov, sm);
    float cx  = 1.f + 2.f * xy + y2;
    float cy  = 1.f - x2o;
    float den = fmaxf(fmaf(x2o, y2, 1.f + 2.f * xy), 1e-15f);
    out[(size_t)row * UU + t] = (cx * ov + cy * bvx) / den;
}

// ============================================================
extern "C" void kernel_launch(void* const* d_in, const int* in_sizes, int n_in,
                              void* d_out, int out_size) {
    const float* feat = (const float*)d_in[0];
    const int*   adj  = (const int*)  d_in[1];
    const float* W    = (const float*)d_in[2];
    const float* bias = (const float*)d_in[3];
    float* out = (float*)d_out;

    cudaFuncSetAttribute(k_attn, cudaFuncAttributeMaxDynamicSharedMemorySize, G1_SMEM);
    cudaFuncSetAttribute(k_agg,  cudaFuncAttributeMaxDynamicSharedMemorySize, G2_SMEM);

    k_adjmask <<<NN * NN / 32 / 256, 256>>>(adj);
    k_gemmA   <<<NN / 16, 256>>>(feat, W);
    k_expmap  <<<NN, 128>>>();
    k_attn    <<<512, 256, G1_SMEM>>>();
    k_agg     <<<128, 256, G2_SMEM>>>();
    k_epilogue<<<NN, 128>>>(bias, out);
}

// round 6
// speedup vs baseline: 3.0096x; 1.0710x over previous
#include <cuda_runtime.h>
#include <cuda_bf16.h>
#include <cuda_fp16.h>
#include <cstdint>
#include <math.h>

#define NN 8192
#define DD 256
#define UU 128

// ================= device scratch (no allocations allowed) =================
__device__ __align__(256) float          g_buf[NN * UU];     // stage1: u = feat@W
__device__ __align__(256) __half         g_xh[NN * UU];      // fp16 split of x (node-major)
__device__ __align__(256) __half         g_xl[NN * UU];
__device__ __align__(256) __nv_bfloat16  g_xTh[UU * NN];     // bf16 split of x, transposed
__device__ __align__(256) __nv_bfloat16  g_xTl[UU * NN];
__device__ __align__(256) float          g_x2[NN];
__device__ __align__(256) unsigned int   g_w[(size_t)NN * NN];   // packed (w_hi | w_lo<<16) bf16
__device__ __align__(256) uint32_t       g_adjb[(size_t)NN * NN / 32]; // adjacency bitmask
__device__ __align__(256) float          g_rsump[NN * 8];         // per (i, j-quarter) sums
__device__ __align__(256) float          g_mx2[2 * NN * UU];      // ksplit halves of mx

// ======================= helpers =======================
__device__ __forceinline__ uint32_t smem_to_u32(const void* p) {
    uint32_t a;
    asm("{ .reg .u64 t; cvta.to.shared.u64 t, %1; cvt.u32.u64 %0, t; }"
        : "=r"(a) : "l"(p));
    return a;
}
__device__ __forceinline__ void cp16(uint32_t saddr, const void* gaddr) {
    asm volatile("cp.async.cg.shared.global [%0], [%1], 16;"
                 :: "r"(saddr), "l"(gaddr));
}
#define CP_COMMIT() asm volatile("cp.async.commit_group;" ::: "memory")
#define CP_WAIT0()  asm volatile("cp.async.wait_group 0;" ::: "memory")

__device__ __forceinline__ void ldsm4(uint32_t& r0, uint32_t& r1, uint32_t& r2,
                                      uint32_t& r3, uint32_t addr) {
    asm volatile("ldmatrix.sync.aligned.m8n8.x4.shared.b16 {%0,%1,%2,%3}, [%4];"
                 : "=r"(r0), "=r"(r1), "=r"(r2), "=r"(r3) : "r"(addr));
}
__device__ __forceinline__ void mma_f16(float* d, const uint32_t* a,
                                        uint32_t b0, uint32_t b1) {
    asm volatile("mma.sync.aligned.m16n8k16.row.col.f32.f16.f16.f32 "
                 "{%0,%1,%2,%3}, {%4,%5,%6,%7}, {%8,%9}, {%0,%1,%2,%3};"
                 : "+f"(d[0]), "+f"(d[1]), "+f"(d[2]), "+f"(d[3])
                 : "r"(a[0]), "r"(a[1]), "r"(a[2]), "r"(a[3]), "r"(b0), "r"(b1));
}
__device__ __forceinline__ void mma_bf16(float* d, const uint32_t* a,
                                         uint32_t b0, uint32_t b1) {
    asm volatile("mma.sync.aligned.m16n8k16.row.col.f32.bf16.bf16.f32 "
                 "{%0,%1,%2,%3}, {%4,%5,%6,%7}, {%8,%9}, {%0,%1,%2,%3};"
                 : "+f"(d[0]), "+f"(d[1]), "+f"(d[2]), "+f"(d[3])
                 : "r"(a[0]), "r"(a[1]), "r"(a[2]), "r"(a[3]), "r"(b0), "r"(b1));
}

__device__ __forceinline__ float blockReduce128(float v, volatile float* sm) {
    #pragma unroll
    for (int o = 16; o > 0; o >>= 1) v += __shfl_xor_sync(0xffffffffu, v, o);
    if ((threadIdx.x & 31) == 0) sm[threadIdx.x >> 5] = v;
    __syncthreads();
    float r = sm[0] + sm[1] + sm[2] + sm[3];
    __syncthreads();
    return r;
}

// w = exp(hyperbolic distance), closed form; masked by adjacency / dist==0
__device__ __forceinline__ float score_w(float xy, float x2i, float x2j, int am) {
    float A = 1.f - 2.f * xy + x2j;
    float B = 1.f - x2i;
    float num = fmaf(A * A, x2i, fmaf(-2.f * A * B, xy, B * B * x2j));
    num = fmaxf(num, 0.f);
    float den = fmaxf(fmaf(x2i, x2j, 1.f - 2.f * xy), 1e-15f);
    float sq  = sqrtf(num);
    float w;
    if (sq < (1.f - 1e-7f) * den) w = (den + sq) / (den - sq);
    else                          w = (2.f - 1e-7f) / 1e-7f;
    if (am == 0 || !(sq > 0.f)) w = 0.f;
    return w;
}
__device__ __forceinline__ unsigned pack_w(float w) {
    __nv_bfloat16 bh = __float2bfloat16(w);
    __nv_bfloat16 bl = __float2bfloat16(w - __bfloat162float(bh));
    return (unsigned)__bfloat16_as_ushort(bh) |
           ((unsigned)__bfloat16_as_ushort(bl) << 16);
}

// ============================================================
// Stage 0: adjacency -> bitmask (1 thread per 32 ints)
// ============================================================
__global__ __launch_bounds__(256) void k_adjmask(const int* __restrict__ adj) {
    size_t w = (size_t)blockIdx.x * 256 + threadIdx.x;
    const int4* p = (const int4*)(adj + w * 32);
    uint32_t m = 0;
    #pragma unroll
    for (int q = 0; q < 8; q++) {
        int4 v = p[q];
        m |= (v.x != 0 ? 1u : 0u) << (q * 4 + 0);
        m |= (v.y != 0 ? 1u : 0u) << (q * 4 + 1);
        m |= (v.z != 0 ? 1u : 0u) << (q * 4 + 2);
        m |= (v.w != 0 ? 1u : 0u) << (q * 4 + 3);
    }
    g_adjb[w] = m;
}

// ============================================================
// Stage 1: u = features @ kernel
// ============================================================
__global__ __launch_bounds__(256) void k_gemmA(const float* __restrict__ feat,
                                               const float* __restrict__ W) {
    __shared__ float fs[16][DD];
    int tid = threadIdx.x;
    int r0  = blockIdx.x * 16;
    for (int idx = tid; idx < 16 * DD; idx += 256)
        fs[idx >> 8][idx & 255] = feat[(size_t)(r0 + (idx >> 8)) * DD + (idx & 255)];
    __syncthreads();
    int col = tid & 127, rg = tid >> 7;
    float acc[8] = {0.f,0.f,0.f,0.f,0.f,0.f,0.f,0.f};
    for (int d = 0; d < DD; d++) {
        float kv = W[d * UU + col];
        #pragma unroll
        for (int r = 0; r < 8; r++)
            acc[r] = fmaf(fs[rg * 8 + r][d], kv, acc[r]);
    }
    #pragma unroll
    for (int r = 0; r < 8; r++)
        g_buf[(size_t)(r0 + rg * 8 + r) * UU + col] = acc[r];
}

// ============================================================
// Stage 2: x = expmap0(u); fp16 split, bf16 transposed split, x2
// ============================================================
__global__ __launch_bounds__(128) void k_expmap() {
    __shared__ float sm[4];
    int row = blockIdx.x, t = threadIdx.x;
    float v  = g_buf[(size_t)row * UU + t];
    float n2 = blockReduce128(v * v, sm);
    float n  = fmaxf(sqrtf(n2), 1e-15f);
    float xv = tanhf(n) / n * v;

    __half hh = __float2half(xv);
    __half hl = __float2half(xv - __half2float(hh));
    g_xh[(size_t)row * UU + t] = hh;
    g_xl[(size_t)row * UU + t] = hl;

    __nv_bfloat16 bh = __float2bfloat16(xv);
    __nv_bfloat16 bl = __float2bfloat16(xv - __bfloat162float(bh));
    g_xTh[(size_t)t * NN + row] = bh;
    g_xTl[(size_t)t * NN + row] = bl;

    float s2 = blockReduce128(xv * xv, sm);
    if (t == 0) g_x2[row] = s2;
}

// ============================================================
// Stage 3 (k_attn): persistent, cp.async double-buffered, 512 threads.
// grid 512 = 64 ib x 8 jq; warp grid 8(m16) x 2(n64).
// smem: [Ahi][Alo][Bhi0][Blo0][Bhi1][Blo1] + rsum combine area.
// ============================================================
#define SKA 136
#define ATILE (128 * SKA * 2)          /* 34816 B */
#define RS_OFF (6 * ATILE)
#define G1_SMEM (6 * ATILE + 1024)

__device__ __forceinline__ void cp_tile16_512(char* dst, const __half* src,
                                              int r0, int tid) {
    #pragma unroll
    for (int it = 0; it < 4; it++) {
        int idx = it * 512 + tid;
        int row = idx >> 4, q = idx & 15;
        cp16(smem_to_u32(dst + (row * SKA + q * 8) * 2),
             (const void*)(src + (size_t)(r0 + row) * UU + q * 8));
    }
}

__global__ __launch_bounds__(512) void k_attn() {
    extern __shared__ char smc[];
    uint32_t sb = smem_to_u32(smc);
    int tid = threadIdx.x, wid = tid >> 5, lane = tid & 31;
    int ib = blockIdx.x >> 3, jq = blockIdx.x & 7;
    int i0 = ib * 128;

    int wm = (wid & 7) * 16, wn = (wid >> 3) * 64;
    int g = lane >> 2, tq = lane & 3;
    int aRow = (lane & 7) + ((lane >> 3) & 1) * 8;
    int aCol = (lane >> 4) * 8;
    int bRow = (lane & 7) + (lane >> 4) * 8;
    int bCol = ((lane >> 3) & 1) * 8;

    // prologue: A hi/lo resident + B(c=0) hi/lo
    cp_tile16_512(smc + 0 * ATILE, g_xh, i0, tid);
    cp_tile16_512(smc + 1 * ATILE, g_xl, i0, tid);
    cp_tile16_512(smc + 2 * ATILE, g_xh, jq * 1024, tid);
    cp_tile16_512(smc + 3 * ATILE, g_xl, jq * 1024, tid);
    CP_COMMIT();

    float x2i[2];
    x2i[0] = g_x2[i0 + wm + g];
    x2i[1] = g_x2[i0 + wm + g + 8];

    float rsum[2] = {0.f, 0.f};

    CP_WAIT0();
    __syncthreads();

    for (int c = 0; c < 8; c++) {
        int s = c & 1;
        if (c < 7) {   // prefetch next j-tile into the other stage
            int jn = jq * 1024 + (c + 1) * 128;
            cp_tile16_512(smc + (2 + 2 * (s ^ 1)) * ATILE, g_xh, jn, tid);
            cp_tile16_512(smc + (3 + 2 * (s ^ 1)) * ATILE, g_xl, jn, tid);
            CP_COMMIT();
        }

        // ---- MMA: 3 products (hi*hi + hi*lo + lo*hi) ----
        float acc[8][4];
        #pragma unroll
        for (int nb = 0; nb < 8; nb++)
            #pragma unroll
            for (int q = 0; q < 4; q++) acc[nb][q] = 0.f;

        #pragma unroll
        for (int p = 0; p < 3; p++) {
            uint32_t Ab = sb + (p == 2 ? ATILE : 0);
            uint32_t Bb = sb + (uint32_t)(2 + 2 * s + (p == 1 ? 1 : 0)) * ATILE;
            #pragma unroll
            for (int ksv = 0; ksv < 8; ksv++) {
                int k0 = ksv * 16;
                uint32_t a[4], b[4][4];
                ldsm4(a[0], a[1], a[2], a[3],
                      Ab + (uint32_t)((wm + aRow) * SKA + k0 + aCol) * 2);
                #pragma unroll
                for (int nb = 0; nb < 4; nb++)
                    ldsm4(b[nb][0], b[nb][1], b[nb][2], b[nb][3],
                          Bb + (uint32_t)((wn + nb * 16 + bRow) * SKA + k0 + bCol) * 2);
                #pragma unroll
                for (int nb = 0; nb < 4; nb++) {
                    mma_f16(acc[2 * nb],     a, b[nb][0], b[nb][1]);
                    mma_f16(acc[2 * nb + 1], a, b[nb][2], b[nb][3]);
                }
            }
        }

        // ---- score epilogue straight from accumulators ----
        int j0c = jq * 1024 + c * 128;
        #pragma unroll
        for (int rh = 0; rh < 2; rh++) {
            int ig = i0 + wm + g + rh * 8;
            uint2 mwv = *(const uint2*)&g_adjb[(size_t)ig * (NN / 32)
                                               + ((j0c + wn) >> 5)];
            float x2iv = x2i[rh];
            float rs = 0.f;
            #pragma unroll
            for (int nbi = 0; nbi < 8; nbi++) {
                int jl = wn + nbi * 8 + 2 * tq;
                int jg = j0c + jl;
                float2 x2jv = *(const float2*)&g_x2[jg];
                uint32_t mword = (nbi < 4) ? mwv.x : mwv.y;
                int sh = jl & 31;
                int a0 = (mword >> sh) & 1;
                int a1 = (mword >> (sh + 1)) & 1;
                float w0 = score_w(acc[nbi][rh * 2 + 0], x2iv, x2jv.x, a0);
                float w1 = score_w(acc[nbi][rh * 2 + 1], x2iv, x2jv.y, a1);
                *(uint2*)&g_w[(size_t)ig * NN + jg] =
                    make_uint2(pack_w(w0), pack_w(w1));
                rs += w0 + w1;
            }
            rsum[rh] += rs;
        }

        if (c < 7) CP_WAIT0();
        __syncthreads();
    }

    // ---- row-sum combine: reduce over tq, then warp pairs ----
    #pragma unroll
    for (int r = 0; r < 2; r++) {
        rsum[r] += __shfl_xor_sync(0xffffffffu, rsum[r], 1);
        rsum[r] += __shfl_xor_sync(0xffffffffu, rsum[r], 2);
    }
    float* RS = (float*)(smc + RS_OFF);    // [16 warps][16 rows]
    if (tq == 0) {
        RS[wid * 16 + g]     = rsum[0];
        RS[wid * 16 + 8 + g] = rsum[1];
    }
    __syncthreads();
    if (tid < 128) {
        int mt = tid >> 4, idx = tid & 15;
        float v = RS[mt * 16 + idx] + RS[(mt + 8) * 16 + idx];
        g_rsump[(i0 + tid) * 8 + jq] = v;
    }
}

// ============================================================
// Stage 4 (k_agg): mx = W @ X, bf16-split HMMA, 512 threads.
// grid 128 (64 i-tiles x ksplit 2), 64-j chunks, double buffer.
// stage layout: [Whi][Wlo][Xhi][Xlo], each 128 x SKC bf16.
// ============================================================
#define SKC 72
#define CT  (128 * SKC * 2)        /* 18432 B */
#define STG (4 * CT)               /* 73728 B */
#define G2_SMEM (2 * STG)          /* 147456 B */

__global__ __launch_bounds__(512) void k_agg() {
    extern __shared__ char smc[];
    uint32_t sb = smem_to_u32(smc);
    int tid = threadIdx.x, wid = tid >> 5, lane = tid & 31;
    int ib = blockIdx.x >> 1, ks = blockIdx.x & 1;
    int i0 = ib * 128, jbeg = ks * 4096;

    int wm = (wid & 7) * 16, wn = (wid >> 3) * 64;
    int aRow = (lane & 7) + ((lane >> 3) & 1) * 8;
    int aCol = (lane >> 4) * 8;
    int bRow = (lane & 7) + (lane >> 4) * 8;
    int bCol = ((lane >> 3) & 1) * 8;

    float acc[8][4];
    #pragma unroll
    for (int nb = 0; nb < 8; nb++)
        #pragma unroll
        for (int q = 0; q < 4; q++) acc[nb][q] = 0.f;

    // ---- X^T cp.async loader (512 threads) ----
    #define CP_X(cc, ss) do {                                                  \
        int jc0 = jbeg + (cc) * 64;                                            \
        char* st = smc + (ss) * STG;                                           \
        _Pragma("unroll")                                                      \
        for (int it = 0; it < 2; it++) {                                       \
            int idx = it * 512 + tid;                                          \
            int row = idx >> 3, q = idx & 7;                                   \
            int off = (row * SKC + q * 8) * 2;                                 \
            cp16(smem_to_u32(st + 2 * CT + off),                               \
                 (const void*)(g_xTh + (size_t)row * NN + jc0 + q * 8));       \
            cp16(smem_to_u32(st + 3 * CT + off),                               \
                 (const void*)(g_xTl + (size_t)row * NN + jc0 + q * 8));       \
        }                                                                      \
    } while (0)

    // ---- W loaders: LDG to regs / perm+STS from regs ----
    #define LDG_W(cc, vreg) do {                                               \
        int jc0 = jbeg + (cc) * 64;                                            \
        _Pragma("unroll")                                                      \
        for (int it = 0; it < 4; it++) {                                       \
            int idx = it * 512 + tid;                                          \
            int row = idx >> 4, q = idx & 15;                                  \
            (vreg)[it] = *(const uint4*)(g_w + (size_t)(i0 + row) * NN         \
                                         + jc0 + q * 4);                       \
        }                                                                      \
    } while (0)
    #define STS_W(ss, vreg) do {                                               \
        char* st = smc + (ss) * STG;                                           \
        _Pragma("unroll")                                                      \
        for (int it = 0; it < 4; it++) {                                       \
            int idx = it * 512 + tid;                                          \
            int row = idx >> 4, q = idx & 15;                                  \
            unsigned h01 = __byte_perm((vreg)[it].x, (vreg)[it].y, 0x5410);    \
            unsigned h23 = __byte_perm((vreg)[it].z, (vreg)[it].w, 0x5410);    \
            unsigned l01 = __byte_perm((vreg)[it].x, (vreg)[it].y, 0x7632);    \
            unsigned l23 = __byte_perm((vreg)[it].z, (vreg)[it].w, 0x7632);    \
            int off = (row * SKC + q * 4) * 2;                                 \
            *(uint2*)(st + off)      = make_uint2(h01, h23);                   \
            *(uint2*)(st + CT + off) = make_uint2(l01, l23);                   \
        }                                                                      \
    } while (0)

    // prologue: chunk 0
    uint4 vW[4];
    CP_X(0, 0);
    CP_COMMIT();
    LDG_W(0, vW);
    STS_W(0, vW);
    CP_WAIT0();
    __syncthreads();

    for (int c = 0; c < 64; c++) {
        int s = c & 1;
        if (c < 63) {
            CP_X(c + 1, s ^ 1);
            CP_COMMIT();
            LDG_W(c + 1, vW);     // LDG latency hidden behind MMAs below
        }

        uint32_t stb = sb + s * STG;
        #pragma unroll
        for (int p = 0; p < 3; p++) {
            uint32_t Ab = stb + (p == 2 ? CT : 0);            // W: hi, hi, lo
            uint32_t Bb = stb + 2 * CT + (p == 1 ? CT : 0);   // X: hi, lo, hi
            #pragma unroll
            for (int ksv = 0; ksv < 4; ksv++) {
                int k0 = ksv * 16;
                uint32_t a[4], b[4][4];
                ldsm4(a[0], a[1], a[2], a[3],
                      Ab + (uint32_t)((wm + aRow) * SKC + k0 + aCol) * 2);
                #pragma unroll
                for (int nb = 0; nb < 4; nb++)
                    ldsm4(b[nb][0], b[nb][1], b[nb][2], b[nb][3],
                          Bb + (uint32_t)((wn + nb * 16 + bRow) * SKC + k0 + bCol) * 2);
                #pragma unroll
                for (int nb = 0; nb < 4; nb++) {
                    mma_bf16(acc[2 * nb],     a, b[nb][0], b[nb][1]);
                    mma_bf16(acc[2 * nb + 1], a, b[nb][2], b[nb][3]);
                }
            }
        }

        if (c < 63) STS_W(s ^ 1, vW);
        CP_WAIT0();
        __syncthreads();
    }

    // ---- writeback (each (i,d) owned by exactly one CTA per ksplit half) ----
    int g = lane >> 2, tq = lane & 3;
    #pragma unroll
    for (int nbi = 0; nbi < 8; nbi++) {
        int irow = i0 + wm + g;
        int dcol = wn + nbi * 8 + 2 * tq;
        *(float2*)&g_mx2[((size_t)ks * NN + irow) * UU + dcol] =
            make_float2(acc[nbi][0], acc[nbi][1]);
        *(float2*)&g_mx2[((size_t)ks * NN + irow + 8) * UU + dcol] =
            make_float2(acc[nbi][2], acc[nbi][3]);
    }
}

// ============================================================
// Stage 5: combine halves, normalize, hyperbolic rescale + mobius bias add
// ============================================================
__global__ __launch_bounds__(128) void k_epilogue(const float* __restrict__ bias,
                                                  float* __restrict__ out) {
    __shared__ float sm[4];
    int row = blockIdx.x, t = threadIdx.x;

    float rp = (t < 8) ? g_rsump[row * 8 + t] : 0.f;
    float rs = blockReduce128(rp, sm);

    float m = (g_mx2[(size_t)row * UU + t] +
               g_mx2[(size_t)(NN + row) * UU + t]) / rs;
    float mn2 = blockReduce128(m * m, sm);
    float x2i = g_x2[row];
    float x_n  = fmaxf(sqrtf(x2i), 1e-15f);
    float mx_n = fmaxf(sqrtf(mn2), 1e-15f);
    float xa   = fminf(x_n, 1.f - 1e-7f);
    float art  = 0.5f * (log1pf(xa) - log1pf(-xa));
    float alpha = tanhf(mx_n / x_n * art) / mx_n;
    float ov = alpha * m;

    float bv  = bias[t];
    float bn2 = blockReduce128(bv * bv, sm);
    float bn  = fmaxf(sqrtf(bn2), 1e-15f);
    float bvx = tanhf(bn) / bn * bv;

    float y2  = blockReduce128(bvx * bvx, sm);
    float xy  = blockReduce128(ov * bvx, sm);
    float x2o = blockReduce128(ov * ov, sm);
    float cx  = 1.f + 2.f * xy + y2;
    float cy  = 1.f - x2o;
    float den = fmaxf(fmaf(x2o, y2, 1.f + 2.f * xy), 1e-15f);
    out[(size_t)row * UU + t] = (cx * ov + cy * bvx) / den;
}

// ============================================================
extern "C" void kernel_launch(void* const* d_in, const int* in_sizes, int n_in,
                              void* d_out, int out_size) {
    const float* feat = (const float*)d_in[0];
    const int*   adj  = (const int*)  d_in[1];
    const float* W    = (const float*)d_in[2];
    const float* bias = (const float*)d_in[3];
    float* out = (float*)d_out;

    cudaFuncSetAttribute(k_attn, cudaFuncAttributeMaxDynamicSharedMemorySize, G1_SMEM);
    cudaFuncSetAttribute(k_agg,  cudaFuncAttributeMaxDynamicSharedMemorySize, G2_SMEM);

    k_adjmask <<<NN * NN / 32 / 256, 256>>>(adj);
    k_gemmA   <<<NN / 16, 256>>>(feat, W);
    k_expmap  <<<NN, 128>>>();
    k_attn    <<<512, 512, G1_SMEM>>>();
    k_agg     <<<128, 512, G2_SMEM>>>();
    k_epilogue<<<NN, 128>>>(bias, out);
}